// round 1
// baseline (speedup 1.0000x reference)
#include <cuda_runtime.h>
#include <math.h>

// Problem constants
#define Bb   32
#define Nn   320
#define Cc   768
#define Hh   12
#define HDd  64
#define MLPH 3072
#define LT   64
#define LS   256
#define MROWS (Bb*Nn)          // 10240
#define C3   (3*Cc)            // 2304
#define LNEPS 1e-5f

// ---------------- scratch (static device globals; no runtime alloc) --------
__device__ float g_xn  [(size_t)MROWS*Cc];
__device__ float g_qkv [(size_t)MROWS*C3];
__device__ float g_attn[(size_t)Bb*Hh*Nn*Nn];
__device__ float g_ctx [(size_t)MROWS*Cc];
__device__ float g_x1  [(size_t)MROWS*Cc];
__device__ float g_h   [(size_t)MROWS*MLPH];
__device__ float g_x2  [(size_t)MROWS*Cc];
__device__ float g_wts [(size_t)Bb*LT*LS];
__device__ float g_sup [(size_t)MROWS*Cc];
__device__ float g_xg  [(size_t)MROWS*Cc];

// ---------------- LayerNorm: one block per row (768 cols, 256 thr) ---------
template<bool ADDX>
__global__ void ln_kernel(const float* __restrict__ x,
                          const float* __restrict__ g,
                          const float* __restrict__ b,
                          float* __restrict__ out) {
    const int row = blockIdx.x;
    const float* xr = x + (size_t)row * Cc;
    float v[3];
    float s = 0.f, sq = 0.f;
#pragma unroll
    for (int j = 0; j < 3; j++) {
        v[j] = xr[threadIdx.x + j*256];
        s += v[j]; sq += v[j]*v[j];
    }
#pragma unroll
    for (int o = 16; o > 0; o >>= 1) {
        s  += __shfl_xor_sync(0xffffffffu, s,  o);
        sq += __shfl_xor_sync(0xffffffffu, sq, o);
    }
    __shared__ float ss[8], ssq[8];
    __shared__ float bm, brs;
    const int w = threadIdx.x >> 5;
    if ((threadIdx.x & 31) == 0) { ss[w] = s; ssq[w] = sq; }
    __syncthreads();
    if (threadIdx.x == 0) {
        float a = 0.f, aq = 0.f;
#pragma unroll
        for (int i = 0; i < 8; i++) { a += ss[i]; aq += ssq[i]; }
        const float m = a * (1.f/Cc);
        bm  = m;
        brs = rsqrtf(aq * (1.f/Cc) - m*m + LNEPS);
    }
    __syncthreads();
    const float m = bm, rs = brs;
    float* outr = out + (size_t)row * Cc;
#pragma unroll
    for (int j = 0; j < 3; j++) {
        const int c = threadIdx.x + j*256;
        const float r = (v[j] - m) * rs * g[c] + b[c];
        outr[c] = ADDX ? (v[j] + r) : r;
    }
}

// ---------------- SGEMM 128x128x8, 256 thr, 8x8/thread ---------------------
// EPI bit0: +bias   bit2: gelu(exact)   bit1: +residual (stride = Nd)
template<int EPI>
__global__ void __launch_bounds__(256, 2)
sgemm_kernel(const float* __restrict__ A, const float* __restrict__ W,
             const float* __restrict__ bias, const float* __restrict__ res,
             float* __restrict__ Cout, int M, int Nd, int K) {
    __shared__ float As[8][128];
    __shared__ float Bs[8][128];
    const int t  = threadIdx.x;
    const int m0 = blockIdx.y * 128, n0 = blockIdx.x * 128;
    const int ar = t >> 1,  ac = (t & 1) * 4;
    const int br = t >> 5,  bc = (t & 31) * 4;
    const int tx = t & 15,  ty = t >> 4;

    float acc[8][8];
#pragma unroll
    for (int i = 0; i < 8; i++)
#pragma unroll
        for (int j = 0; j < 8; j++) acc[i][j] = 0.f;

    const float* Ap = A + (size_t)(m0 + ar) * K + ac;
    const float* Wp = W + (size_t)br * Nd + n0 + bc;

    for (int kt = 0; kt < K; kt += 8) {
        const float4 av = *(const float4*)(Ap + kt);
        const float4 bv = *(const float4*)(Wp + (size_t)kt * Nd);
        As[ac+0][ar] = av.x; As[ac+1][ar] = av.y;
        As[ac+2][ar] = av.z; As[ac+3][ar] = av.w;
        *(float4*)&Bs[br][bc] = bv;
        __syncthreads();
#pragma unroll
        for (int k = 0; k < 8; k++) {
            const float4 a0 = *(const float4*)&As[k][ty*4];
            const float4 a1 = *(const float4*)&As[k][ty*4 + 64];
            const float4 b0 = *(const float4*)&Bs[k][tx*4];
            const float4 b1 = *(const float4*)&Bs[k][tx*4 + 64];
            const float ai[8] = {a0.x,a0.y,a0.z,a0.w,a1.x,a1.y,a1.z,a1.w};
            const float bj[8] = {b0.x,b0.y,b0.z,b0.w,b1.x,b1.y,b1.z,b1.w};
#pragma unroll
            for (int i = 0; i < 8; i++)
#pragma unroll
                for (int j = 0; j < 8; j++) acc[i][j] += ai[i]*bj[j];
        }
        __syncthreads();
    }

#pragma unroll
    for (int i = 0; i < 8; i++) {
        const int r = m0 + ((i < 4) ? (ty*4 + i) : (64 + ty*4 + (i-4)));
#pragma unroll
        for (int j = 0; j < 8; j++) {
            const int c = n0 + ((j < 4) ? (tx*4 + j) : (64 + tx*4 + (j-4)));
            float v = acc[i][j];
            if (EPI & 1) v += bias[c];
            if (EPI & 4) v = 0.5f * v * (1.f + erff(v * 0.70710678118654752f));
            if (EPI & 2) v += res[(size_t)r * Nd + c];
            Cout[(size_t)r * Nd + c] = v;
        }
    }
}

// ---------------- attention logits: q @ k^T * scale ------------------------
// grid (5 n-tiles, 5 m-tiles, B*H), block 256
__global__ void logits_kernel() {
    __shared__ float Qs[64][65];
    __shared__ float Ks[64][65];
    const int bh = blockIdx.z;
    const int b = bh / Hh, h = bh % Hh;
    const int n0 = blockIdx.x * 64, m0 = blockIdx.y * 64;
    const int t = threadIdx.x;
    for (int idx = t; idx < 4096; idx += 256) {
        const int r = idx >> 6, d = idx & 63;
        Qs[r][d] = g_qkv[(size_t)(b*Nn + n0 + r)*C3 + 0*Cc + h*HDd + d];
        Ks[r][d] = g_qkv[(size_t)(b*Nn + m0 + r)*C3 + 1*Cc + h*HDd + d];
    }
    __syncthreads();
    const int tx = t & 15, ty = t >> 4;
    float acc[4][4] = {};
#pragma unroll 4
    for (int d = 0; d < 64; d++) {
        float a[4], kk[4];
#pragma unroll
        for (int i = 0; i < 4; i++) a[i]  = Qs[ty*4 + i][d];
#pragma unroll
        for (int j = 0; j < 4; j++) kk[j] = Ks[tx*4 + j][d];
#pragma unroll
        for (int i = 0; i < 4; i++)
#pragma unroll
            for (int j = 0; j < 4; j++) acc[i][j] += a[i]*kk[j];
    }
    const float scale = 0.125f;  // 1/sqrt(64)
#pragma unroll
    for (int i = 0; i < 4; i++)
#pragma unroll
        for (int j = 0; j < 4; j++)
            g_attn[((size_t)bh*Nn + n0 + ty*4 + i)*Nn + m0 + tx*4 + j] =
                acc[i][j] * scale;
}

// ---------------- row softmax over attn (len 320), block 320 ----------------
__global__ void softmax_attn_kernel() {
    const size_t row = blockIdx.x;
    float* p = g_attn + row * (size_t)Nn;
    const int t = threadIdx.x;
    const float v = p[t];
    __shared__ float rbuf[10];
    __shared__ float bmax, bsum;
    float m = v;
#pragma unroll
    for (int o = 16; o > 0; o >>= 1) m = fmaxf(m, __shfl_xor_sync(0xffffffffu, m, o));
    if ((t & 31) == 0) rbuf[t >> 5] = m;
    __syncthreads();
    if (t < 32) {
        float mm = (t < 10) ? rbuf[t] : -1e30f;
#pragma unroll
        for (int o = 16; o > 0; o >>= 1) mm = fmaxf(mm, __shfl_xor_sync(0xffffffffu, mm, o));
        if (t == 0) bmax = mm;
    }
    __syncthreads();
    const float e = expf(v - bmax);
    float s = e;
#pragma unroll
    for (int o = 16; o > 0; o >>= 1) s += __shfl_xor_sync(0xffffffffu, s, o);
    __syncthreads();
    if ((t & 31) == 0) rbuf[t >> 5] = s;
    __syncthreads();
    if (t < 32) {
        float ss = (t < 10) ? rbuf[t] : 0.f;
#pragma unroll
        for (int o = 16; o > 0; o >>= 1) ss += __shfl_xor_sync(0xffffffffu, ss, o);
        if (t == 0) bsum = ss;
    }
    __syncthreads();
    p[t] = e / bsum;
}

// ---------------- ctx = attn @ v : grid (5 n-tiles, B*H), block 256 ---------
__global__ void ctx_kernel() {
    __shared__ float As[64][65];
    __shared__ float Vs[64][65];
    const int bh = blockIdx.y;
    const int b = bh / Hh, h = bh % Hh;
    const int n0 = blockIdx.x * 64;
    const int t = threadIdx.x, tx = t & 15, ty = t >> 4;
    float acc[4][4] = {};
    for (int m0 = 0; m0 < Nn; m0 += 64) {
        for (int idx = t; idx < 4096; idx += 256) {
            const int r = idx >> 6, c = idx & 63;
            As[r][c] = g_attn[((size_t)bh*Nn + n0 + r)*Nn + m0 + c];
            Vs[r][c] = g_qkv[(size_t)(b*Nn + m0 + r)*C3 + 2*Cc + h*HDd + c];
        }
        __syncthreads();
#pragma unroll 4
        for (int m = 0; m < 64; m++) {
            float a[4], vv[4];
#pragma unroll
            for (int i = 0; i < 4; i++) a[i]  = As[ty*4 + i][m];
#pragma unroll
            for (int j = 0; j < 4; j++) vv[j] = Vs[m][tx*4 + j];
#pragma unroll
            for (int i = 0; i < 4; i++)
#pragma unroll
                for (int j = 0; j < 4; j++) acc[i][j] += a[i]*vv[j];
        }
        __syncthreads();
    }
#pragma unroll
    for (int i = 0; i < 4; i++)
#pragma unroll
        for (int j = 0; j < 4; j++)
            g_ctx[(size_t)(b*Nn + n0 + ty*4 + i)*Cc + h*HDd + tx*4 + j] = acc[i][j];
}

// ---------------- w_ts: head-mean of attn[:, :, :LT, LT:], softmax over s ---
// grid B*LT, block 256 (one thread per s)
__global__ void wts_kernel() {
    const int b  = blockIdx.x / LT;
    const int tq = blockIdx.x % LT;
    const int s  = threadIdx.x;
    float a = 0.f;
#pragma unroll
    for (int h = 0; h < Hh; h++)
        a += g_attn[((size_t)(b*Hh + h)*Nn + tq)*Nn + LT + s];
    a *= (1.f / Hh);
    __shared__ float rbuf[8];
    __shared__ float bmax, bsum;
    float m = a;
#pragma unroll
    for (int o = 16; o > 0; o >>= 1) m = fmaxf(m, __shfl_xor_sync(0xffffffffu, m, o));
    if ((s & 31) == 0) rbuf[s >> 5] = m;
    __syncthreads();
    if (s < 32) {
        float mm = (s < 8) ? rbuf[s] : -1e30f;
#pragma unroll
        for (int o = 4; o > 0; o >>= 1) mm = fmaxf(mm, __shfl_xor_sync(0xffffffffu, mm, o));
        if (s == 0) bmax = mm;
    }
    __syncthreads();
    const float e = expf(a - bmax);
    float su = e;
#pragma unroll
    for (int o = 16; o > 0; o >>= 1) su += __shfl_xor_sync(0xffffffffu, su, o);
    __syncthreads();
    if ((s & 31) == 0) rbuf[s >> 5] = su;
    __syncthreads();
    if (s < 32) {
        float ss = (s < 8) ? rbuf[s] : 0.f;
#pragma unroll
        for (int o = 4; o > 0; o >>= 1) ss += __shfl_xor_sync(0xffffffffu, ss, o);
        if (s == 0) bsum = ss;
    }
    __syncthreads();
    g_wts[((size_t)b*LT + tq)*LS + s] = e / bsum;
}

// ---------------- graph conv: xg = adj @ support (block-sparse) -------------
// rows [0,LT): xg[b,t,:] = sum_s w[b,t,s] * sup[b,LT+s,:]   grid B*LT
__global__ void xg_top_kernel() {
    const int b  = blockIdx.x / LT;
    const int tq = blockIdx.x % LT;
    __shared__ float w[LS];
    w[threadIdx.x] = g_wts[((size_t)b*LT + tq)*LS + threadIdx.x];
    __syncthreads();
    float a0 = 0.f, a1 = 0.f, a2 = 0.f;
    const float* base = g_sup + (size_t)(b*Nn + LT)*Cc + threadIdx.x;
    for (int s = 0; s < LS; s++) {
        const float ws = w[s];
        const float* sup = base + (size_t)s*Cc;
        a0 += ws * sup[0];
        a1 += ws * sup[256];
        a2 += ws * sup[512];
    }
    float* o = g_xg + (size_t)(b*Nn + tq)*Cc + threadIdx.x;
    o[0] = a0; o[256] = a1; o[512] = a2;
}
// rows [LT,N): xg[b,LT+s,:] = sum_t w[b,t,s] * sup[b,t,:]    grid B*LS
__global__ void xg_bot_kernel() {
    const int b = blockIdx.x / LS;
    const int s = blockIdx.x % LS;
    __shared__ float w[LT];
    if (threadIdx.x < LT)
        w[threadIdx.x] = g_wts[((size_t)b*LT + threadIdx.x)*LS + s];
    __syncthreads();
    float a0 = 0.f, a1 = 0.f, a2 = 0.f;
    const float* base = g_sup + (size_t)(b*Nn)*Cc + threadIdx.x;
    for (int tq = 0; tq < LT; tq++) {
        const float wt = w[tq];
        const float* sup = base + (size_t)tq*Cc;
        a0 += wt * sup[0];
        a1 += wt * sup[256];
        a2 += wt * sup[512];
    }
    float* o = g_xg + (size_t)(b*Nn + LT + s)*Cc + threadIdx.x;
    o[0] = a0; o[256] = a1; o[512] = a2;
}

// ---------------------------------------------------------------------------
extern "C" void kernel_launch(void* const* d_in, const int* in_sizes, int n_in,
                              void* d_out, int out_size) {
    const float* x     = (const float*)d_in[0];
    // d_in[1], d_in[2]: unused index tensors
    const float* g1    = (const float*)d_in[3];
    const float* b1    = (const float*)d_in[4];
    const float* Wqkv  = (const float*)d_in[5];
    const float* Wproj = (const float*)d_in[6];
    const float* bproj = (const float*)d_in[7];
    const float* g2    = (const float*)d_in[8];
    const float* b2    = (const float*)d_in[9];
    const float* W1    = (const float*)d_in[10];
    const float* bm1   = (const float*)d_in[11];
    const float* W2    = (const float*)d_in[12];
    const float* bm2   = (const float*)d_in[13];
    const float* Wg    = (const float*)d_in[14];
    const float* bg    = (const float*)d_in[15];
    const float* g3    = (const float*)d_in[16];
    const float* b3    = (const float*)d_in[17];
    float* out = (float*)d_out;

    float *xn, *qkv, *attnp, *ctx, *x1, *hbuf, *x2, *sup, *xg;
    cudaGetSymbolAddress((void**)&xn,   g_xn);
    cudaGetSymbolAddress((void**)&qkv,  g_qkv);
    cudaGetSymbolAddress((void**)&attnp,g_attn);
    cudaGetSymbolAddress((void**)&ctx,  g_ctx);
    cudaGetSymbolAddress((void**)&x1,   g_x1);
    cudaGetSymbolAddress((void**)&hbuf, g_h);
    cudaGetSymbolAddress((void**)&x2,   g_x2);
    cudaGetSymbolAddress((void**)&sup,  g_sup);
    cudaGetSymbolAddress((void**)&xg,   g_xg);

    // 1. xn = LN(x)
    ln_kernel<false><<<MROWS, 256>>>(x, g1, b1, xn);
    // 2. qkv = xn @ Wqkv
    sgemm_kernel<0><<<dim3(C3/128, MROWS/128), 256>>>(xn, Wqkv, nullptr, nullptr,
                                                      qkv, MROWS, C3, Cc);
    // 3. logits (scaled) -> g_attn
    logits_kernel<<<dim3(Nn/64, Nn/64, Bb*Hh), 256>>>();
    // 4. softmax rows
    softmax_attn_kernel<<<Bb*Hh*Nn, Nn>>>();
    // 5. ctx = attn @ v
    ctx_kernel<<<dim3(Nn/64, Bb*Hh), 256>>>();
    // 6. x1 = x + ctx @ Wproj + bproj
    sgemm_kernel<3><<<dim3(Cc/128, MROWS/128), 256>>>(ctx, Wproj, bproj, x,
                                                      x1, MROWS, Cc, Cc);
    // 7. xn = LN(x1)
    ln_kernel<false><<<MROWS, 256>>>(x1, g2, b2, xn);
    // 8. h = gelu(xn @ W1 + bm1)
    sgemm_kernel<5><<<dim3(MLPH/128, MROWS/128), 256>>>(xn, W1, bm1, nullptr,
                                                        hbuf, MROWS, MLPH, Cc);
    // 9. x2 = x1 + h @ W2 + bm2
    sgemm_kernel<3><<<dim3(Cc/128, MROWS/128), 256>>>(hbuf, W2, bm2, x1,
                                                      x2, MROWS, Cc, MLPH);
    // 10. w_ts (head-mean + softmax)
    wts_kernel<<<Bb*LT, 256>>>();
    // 11. support = x2 @ Wg + bg
    sgemm_kernel<1><<<dim3(Cc/128, MROWS/128), 256>>>(x2, Wg, bg, nullptr,
                                                      sup, MROWS, Cc, Cc);
    // 12. xg = adj @ support (block sparse)
    xg_top_kernel<<<Bb*LT, 256>>>();
    xg_bot_kernel<<<Bb*LS, 256>>>();
    // 13. out = xg + LN(xg)
    ln_kernel<true><<<MROWS, 256>>>(xg, g3, b3, out);
}

// round 2
// speedup vs baseline: 1.4624x; 1.4624x over previous
#include <cuda_runtime.h>
#include <mma.h>
#include <math.h>

using namespace nvcuda;

// Problem constants
#define Bb   32
#define Nn   320
#define Cc   768
#define Hh   12
#define HDd  64
#define MLPH 3072
#define LT   64
#define LS   256
#define MROWS (Bb*Nn)          // 10240
#define C3   (3*Cc)            // 2304
#define LNEPS 1e-5f

// ---------------- scratch ----------------------------------------------------
__device__ float g_xn  [(size_t)MROWS*Cc];
__device__ float g_qkv [(size_t)MROWS*C3];
__device__ float g_attn[(size_t)Bb*Hh*Nn*Nn];
__device__ float g_ctx [(size_t)MROWS*Cc];
__device__ float g_x1  [(size_t)MROWS*Cc];
__device__ float g_h   [(size_t)MROWS*MLPH];
__device__ float g_x2  [(size_t)MROWS*Cc];
__device__ float g_wts [(size_t)Bb*LT*LS];
__device__ float g_sup [(size_t)MROWS*Cc];
__device__ float g_xg  [(size_t)MROWS*Cc];

// ---------------- LayerNorm ---------------------------------------------------
template<bool ADDX>
__global__ void ln_kernel(const float* __restrict__ x,
                          const float* __restrict__ g,
                          const float* __restrict__ b,
                          float* __restrict__ out) {
    const int row = blockIdx.x;
    const float* xr = x + (size_t)row * Cc;
    float v[3];
    float s = 0.f, sq = 0.f;
#pragma unroll
    for (int j = 0; j < 3; j++) {
        v[j] = xr[threadIdx.x + j*256];
        s += v[j]; sq += v[j]*v[j];
    }
#pragma unroll
    for (int o = 16; o > 0; o >>= 1) {
        s  += __shfl_xor_sync(0xffffffffu, s,  o);
        sq += __shfl_xor_sync(0xffffffffu, sq, o);
    }
    __shared__ float ss[8], ssq[8];
    __shared__ float bm, brs;
    const int w = threadIdx.x >> 5;
    if ((threadIdx.x & 31) == 0) { ss[w] = s; ssq[w] = sq; }
    __syncthreads();
    if (threadIdx.x == 0) {
        float a = 0.f, aq = 0.f;
#pragma unroll
        for (int i = 0; i < 8; i++) { a += ss[i]; aq += ssq[i]; }
        const float m = a * (1.f/Cc);
        bm  = m;
        brs = rsqrtf(aq * (1.f/Cc) - m*m + LNEPS);
    }
    __syncthreads();
    const float m = bm, rs = brs;
    float* outr = out + (size_t)row * Cc;
#pragma unroll
    for (int j = 0; j < 3; j++) {
        const int c = threadIdx.x + j*256;
        const float r = (v[j] - m) * rs * g[c] + b[c];
        outr[c] = ADDX ? (v[j] + r) : r;
    }
}

// ---------------- TF32 tensor-core GEMM 128x128x32, 256 thr -----------------
// C[M,Nd] = A[M,K] @ W[K,Nd]   (raw; epilogues applied by epi_kernel)
__global__ void __launch_bounds__(256, 2)
gemm_tf32(const float* __restrict__ A, const float* __restrict__ W,
          float* __restrict__ Cout, int M, int Nd, int K) {
    __shared__ float As[128][36];
    __shared__ float Bs[32][132];
    const int t    = threadIdx.x;
    const int warp = t >> 5;
    const int wm   = (warp >> 2) * 64;   // 0 or 64
    const int wn   = (warp & 3) * 32;    // 0,32,64,96
    const int m0   = blockIdx.y * 128, n0 = blockIdx.x * 128;

    wmma::fragment<wmma::accumulator, 16, 16, 8, float> acc[4][2];
#pragma unroll
    for (int i = 0; i < 4; i++)
#pragma unroll
        for (int j = 0; j < 2; j++) wmma::fill_fragment(acc[i][j], 0.f);

    const int ar = t >> 3,  ac = (t & 7) * 4;    // A: 32 rows/pass
    const int br = t >> 5,  bc = (t & 31) * 4;   // B: 8 rows/pass

    for (int kt = 0; kt < K; kt += 32) {
#pragma unroll
        for (int p = 0; p < 4; p++) {
            const float4 v = *(const float4*)(A + (size_t)(m0 + ar + 32*p) * K + kt + ac);
            *(float4*)&As[ar + 32*p][ac] = v;
        }
#pragma unroll
        for (int p = 0; p < 4; p++) {
            const float4 v = *(const float4*)(W + (size_t)(kt + br + 8*p) * Nd + n0 + bc);
            *(float4*)&Bs[br + 8*p][bc] = v;
        }
        __syncthreads();
#pragma unroll
        for (int kk = 0; kk < 4; kk++) {
            const int k8 = kk * 8;
            wmma::fragment<wmma::matrix_a, 16, 16, 8, wmma::precision::tf32, wmma::row_major> a[4];
            wmma::fragment<wmma::matrix_b, 16, 16, 8, wmma::precision::tf32, wmma::row_major> bfr[2];
#pragma unroll
            for (int i = 0; i < 4; i++) {
                wmma::load_matrix_sync(a[i], &As[wm + i*16][k8], 36);
#pragma unroll
                for (int e = 0; e < a[i].num_elements; e++)
                    a[i].x[e] = wmma::__float_to_tf32(a[i].x[e]);
            }
#pragma unroll
            for (int j = 0; j < 2; j++) {
                wmma::load_matrix_sync(bfr[j], &Bs[k8][wn + j*16], 132);
#pragma unroll
                for (int e = 0; e < bfr[j].num_elements; e++)
                    bfr[j].x[e] = wmma::__float_to_tf32(bfr[j].x[e]);
            }
#pragma unroll
            for (int i = 0; i < 4; i++)
#pragma unroll
                for (int j = 0; j < 2; j++)
                    wmma::mma_sync(acc[i][j], a[i], bfr[j], acc[i][j]);
        }
        __syncthreads();
    }
#pragma unroll
    for (int i = 0; i < 4; i++)
#pragma unroll
        for (int j = 0; j < 2; j++)
            wmma::store_matrix_sync(Cout + (size_t)(m0 + wm + i*16) * Nd + n0 + wn + j*16,
                                    acc[i][j], Nd, wmma::mem_row_major);
}

// ---------------- elementwise epilogue: bit0 bias, bit1 +res, bit2 gelu -----
template<int MODE>
__global__ void epi_kernel(float* __restrict__ C, const float* __restrict__ bias,
                           const float* __restrict__ res, int Nd4, size_t total4) {
    const size_t i = (size_t)blockIdx.x * blockDim.x + threadIdx.x;
    if (i >= total4) return;
    float4 v = ((float4*)C)[i];
    const int c4 = (int)(i % Nd4);
    const float4 bb = ((const float4*)bias)[c4];
    v.x += bb.x; v.y += bb.y; v.z += bb.z; v.w += bb.w;
    if (MODE & 4) {
        v.x = 0.5f*v.x*(1.f + erff(v.x*0.70710678118654752f));
        v.y = 0.5f*v.y*(1.f + erff(v.y*0.70710678118654752f));
        v.z = 0.5f*v.z*(1.f + erff(v.z*0.70710678118654752f));
        v.w = 0.5f*v.w*(1.f + erff(v.w*0.70710678118654752f));
    }
    if (MODE & 2) {
        const float4 r = ((const float4*)res)[i];
        v.x += r.x; v.y += r.y; v.z += r.z; v.w += r.w;
    }
    ((float4*)C)[i] = v;
}

// ---------------- attention logits (tf32 wmma): q @ k^T * scale -------------
__global__ void __launch_bounds__(256)
logits_wmma() {
    __shared__ float Qs[64][68];
    __shared__ float Ks[64][68];
    const int bh = blockIdx.z;
    const int b = bh / Hh, h = bh % Hh;
    const int n0 = blockIdx.x * 64, m0 = blockIdx.y * 64;
    const int t = threadIdx.x;
    for (int idx = t; idx < 4096; idx += 256) {
        const int r = idx >> 6, d = idx & 63;
        Qs[r][d] = g_qkv[(size_t)(b*Nn + n0 + r)*C3 + 0*Cc + h*HDd + d];
        Ks[r][d] = g_qkv[(size_t)(b*Nn + m0 + r)*C3 + 1*Cc + h*HDd + d];
    }
    __syncthreads();
    const int warp = t >> 5;
    const int wm = (warp >> 2) * 32;  // 0 or 32
    const int wn = (warp & 3) * 16;   // 0..48
    wmma::fragment<wmma::accumulator, 16, 16, 8, float> acc[2];
    wmma::fill_fragment(acc[0], 0.f);
    wmma::fill_fragment(acc[1], 0.f);
#pragma unroll
    for (int k8 = 0; k8 < 64; k8 += 8) {
        wmma::fragment<wmma::matrix_a, 16, 16, 8, wmma::precision::tf32, wmma::row_major> a[2];
        wmma::fragment<wmma::matrix_b, 16, 16, 8, wmma::precision::tf32, wmma::col_major> bf;
#pragma unroll
        for (int i = 0; i < 2; i++) {
            wmma::load_matrix_sync(a[i], &Qs[wm + i*16][k8], 68);
#pragma unroll
            for (int e = 0; e < a[i].num_elements; e++)
                a[i].x[e] = wmma::__float_to_tf32(a[i].x[e]);
        }
        wmma::load_matrix_sync(bf, &Ks[wn][k8], 68);
#pragma unroll
        for (int e = 0; e < bf.num_elements; e++)
            bf.x[e] = wmma::__float_to_tf32(bf.x[e]);
        wmma::mma_sync(acc[0], a[0], bf, acc[0]);
        wmma::mma_sync(acc[1], a[1], bf, acc[1]);
    }
#pragma unroll
    for (int i = 0; i < 2; i++) {
#pragma unroll
        for (int e = 0; e < acc[i].num_elements; e++) acc[i].x[e] *= 0.125f;
        wmma::store_matrix_sync(g_attn + ((size_t)bh*Nn + n0 + wm + i*16)*Nn + m0 + wn,
                                acc[i], Nn, wmma::mem_row_major);
    }
}

// ---------------- softmax: one warp per row (len 320) -----------------------
__global__ void softmax_warp() {
    const int row  = blockIdx.x * 8 + (threadIdx.x >> 5);
    const int lane = threadIdx.x & 31;
    float* p = g_attn + (size_t)row * Nn;
    float v[10];
    float m = -1e30f;
#pragma unroll
    for (int i = 0; i < 10; i++) { v[i] = p[lane + 32*i]; m = fmaxf(m, v[i]); }
#pragma unroll
    for (int o = 16; o > 0; o >>= 1) m = fmaxf(m, __shfl_xor_sync(0xffffffffu, m, o));
    float s = 0.f;
#pragma unroll
    for (int i = 0; i < 10; i++) { v[i] = expf(v[i] - m); s += v[i]; }
#pragma unroll
    for (int o = 16; o > 0; o >>= 1) s += __shfl_xor_sync(0xffffffffu, s, o);
    const float inv = 1.f / s;
#pragma unroll
    for (int i = 0; i < 10; i++) p[lane + 32*i] = v[i] * inv;
}

// ---------------- ctx = attn @ v (tf32 wmma) --------------------------------
__global__ void __launch_bounds__(256)
ctx_wmma() {
    __shared__ float As[64][68];
    __shared__ float Vs[64][68];
    const int bh = blockIdx.y;
    const int b = bh / Hh, h = bh % Hh;
    const int n0 = blockIdx.x * 64;
    const int t = threadIdx.x;
    const int warp = t >> 5;
    const int wm = (warp >> 2) * 32;
    const int wn = (warp & 3) * 16;
    wmma::fragment<wmma::accumulator, 16, 16, 8, float> acc[2];
    wmma::fill_fragment(acc[0], 0.f);
    wmma::fill_fragment(acc[1], 0.f);
    for (int m0 = 0; m0 < Nn; m0 += 64) {
        for (int idx = t; idx < 4096; idx += 256) {
            const int r = idx >> 6, c = idx & 63;
            As[r][c] = g_attn[((size_t)bh*Nn + n0 + r)*Nn + m0 + c];
            Vs[r][c] = g_qkv[(size_t)(b*Nn + m0 + r)*C3 + 2*Cc + h*HDd + c];
        }
        __syncthreads();
#pragma unroll
        for (int k8 = 0; k8 < 64; k8 += 8) {
            wmma::fragment<wmma::matrix_a, 16, 16, 8, wmma::precision::tf32, wmma::row_major> a[2];
            wmma::fragment<wmma::matrix_b, 16, 16, 8, wmma::precision::tf32, wmma::row_major> bf;
#pragma unroll
            for (int i = 0; i < 2; i++) {
                wmma::load_matrix_sync(a[i], &As[wm + i*16][k8], 68);
#pragma unroll
                for (int e = 0; e < a[i].num_elements; e++)
                    a[i].x[e] = wmma::__float_to_tf32(a[i].x[e]);
            }
            wmma::load_matrix_sync(bf, &Vs[k8][wn], 68);
#pragma unroll
            for (int e = 0; e < bf.num_elements; e++)
                bf.x[e] = wmma::__float_to_tf32(bf.x[e]);
            wmma::mma_sync(acc[0], a[0], bf, acc[0]);
            wmma::mma_sync(acc[1], a[1], bf, acc[1]);
        }
        __syncthreads();
    }
#pragma unroll
    for (int i = 0; i < 2; i++)
        wmma::store_matrix_sync(g_ctx + (size_t)(b*Nn + n0 + wm + i*16)*Cc + h*HDd + wn,
                                acc[i], Cc, wmma::mem_row_major);
}

// ---------------- w_ts: head-mean of attn[:, :, :LT, LT:], softmax over s ---
__global__ void wts_kernel() {
    const int b  = blockIdx.x / LT;
    const int tq = blockIdx.x % LT;
    const int s  = threadIdx.x;
    float a = 0.f;
#pragma unroll
    for (int h = 0; h < Hh; h++)
        a += g_attn[((size_t)(b*Hh + h)*Nn + tq)*Nn + LT + s];
    a *= (1.f / Hh);
    __shared__ float rbuf[8];
    __shared__ float bmax, bsum;
    float m = a;
#pragma unroll
    for (int o = 16; o > 0; o >>= 1) m = fmaxf(m, __shfl_xor_sync(0xffffffffu, m, o));
    if ((s & 31) == 0) rbuf[s >> 5] = m;
    __syncthreads();
    if (s < 32) {
        float mm = (s < 8) ? rbuf[s] : -1e30f;
#pragma unroll
        for (int o = 4; o > 0; o >>= 1) mm = fmaxf(mm, __shfl_xor_sync(0xffffffffu, mm, o));
        if (s == 0) bmax = mm;
    }
    __syncthreads();
    const float e = expf(a - bmax);
    float su = e;
#pragma unroll
    for (int o = 16; o > 0; o >>= 1) su += __shfl_xor_sync(0xffffffffu, su, o);
    __syncthreads();
    if ((s & 31) == 0) rbuf[s >> 5] = su;
    __syncthreads();
    if (s < 32) {
        float ss = (s < 8) ? rbuf[s] : 0.f;
#pragma unroll
        for (int o = 4; o > 0; o >>= 1) ss += __shfl_xor_sync(0xffffffffu, ss, o);
        if (s == 0) bsum = ss;
    }
    __syncthreads();
    g_wts[((size_t)b*LT + tq)*LS + s] = e / bsum;
}

// ---------------- graph conv (block-sparse adj) -----------------------------
__global__ void xg_top_kernel() {
    const int b  = blockIdx.x / LT;
    const int tq = blockIdx.x % LT;
    __shared__ float w[LS];
    w[threadIdx.x] = g_wts[((size_t)b*LT + tq)*LS + threadIdx.x];
    __syncthreads();
    float a0 = 0.f, a1 = 0.f, a2 = 0.f;
    const float* base = g_sup + (size_t)(b*Nn + LT)*Cc + threadIdx.x;
    for (int s = 0; s < LS; s++) {
        const float ws = w[s];
        const float* sup = base + (size_t)s*Cc;
        a0 += ws * sup[0];
        a1 += ws * sup[256];
        a2 += ws * sup[512];
    }
    float* o = g_xg + (size_t)(b*Nn + tq)*Cc + threadIdx.x;
    o[0] = a0; o[256] = a1; o[512] = a2;
}
__global__ void xg_bot_kernel() {
    const int b = blockIdx.x / LS;
    const int s = blockIdx.x % LS;
    __shared__ float w[LT];
    if (threadIdx.x < LT)
        w[threadIdx.x] = g_wts[((size_t)b*LT + threadIdx.x)*LS + s];
    __syncthreads();
    float a0 = 0.f, a1 = 0.f, a2 = 0.f;
    const float* base = g_sup + (size_t)(b*Nn)*Cc + threadIdx.x;
    for (int tq = 0; tq < LT; tq++) {
        const float wt = w[tq];
        const float* sup = base + (size_t)tq*Cc;
        a0 += wt * sup[0];
        a1 += wt * sup[256];
        a2 += wt * sup[512];
    }
    float* o = g_xg + (size_t)(b*Nn + LT + s)*Cc + threadIdx.x;
    o[0] = a0; o[256] = a1; o[512] = a2;
}

// ---------------------------------------------------------------------------
extern "C" void kernel_launch(void* const* d_in, const int* in_sizes, int n_in,
                              void* d_out, int out_size) {
    const float* x     = (const float*)d_in[0];
    const float* g1    = (const float*)d_in[3];
    const float* b1    = (const float*)d_in[4];
    const float* Wqkv  = (const float*)d_in[5];
    const float* Wproj = (const float*)d_in[6];
    const float* bproj = (const float*)d_in[7];
    const float* g2    = (const float*)d_in[8];
    const float* b2    = (const float*)d_in[9];
    const float* W1    = (const float*)d_in[10];
    const float* bm1   = (const float*)d_in[11];
    const float* W2    = (const float*)d_in[12];
    const float* bm2   = (const float*)d_in[13];
    const float* Wg    = (const float*)d_in[14];
    const float* bg    = (const float*)d_in[15];
    const float* g3    = (const float*)d_in[16];
    const float* b3    = (const float*)d_in[17];
    float* out = (float*)d_out;

    float *xn, *qkv, *ctx, *x1, *hbuf, *x2, *sup, *xg;
    cudaGetSymbolAddress((void**)&xn,   g_xn);
    cudaGetSymbolAddress((void**)&qkv,  g_qkv);
    cudaGetSymbolAddress((void**)&ctx,  g_ctx);
    cudaGetSymbolAddress((void**)&x1,   g_x1);
    cudaGetSymbolAddress((void**)&hbuf, g_h);
    cudaGetSymbolAddress((void**)&x2,   g_x2);
    cudaGetSymbolAddress((void**)&sup,  g_sup);
    cudaGetSymbolAddress((void**)&xg,   g_xg);

    // 1. xn = LN(x)
    ln_kernel<false><<<MROWS, 256>>>(x, g1, b1, xn);
    // 2. qkv = xn @ Wqkv
    gemm_tf32<<<dim3(C3/128, MROWS/128), 256>>>(xn, Wqkv, qkv, MROWS, C3, Cc);
    // 3. logits
    logits_wmma<<<dim3(Nn/64, Nn/64, Bb*Hh), 256>>>();
    // 4. softmax
    softmax_warp<<<Bb*Hh*Nn/8, 256>>>();
    // 5. ctx = attn @ v
    ctx_wmma<<<dim3(Nn/64, Bb*Hh), 256>>>();
    // 6. x1 = x + ctx @ Wproj + bproj
    gemm_tf32<<<dim3(Cc/128, MROWS/128), 256>>>(ctx, Wproj, x1, MROWS, Cc, Cc);
    {
        size_t t4 = (size_t)MROWS*Cc/4;
        epi_kernel<3><<<(unsigned)((t4 + 255)/256), 256>>>(x1, bproj, x, Cc/4, t4);
    }
    // 7. xn = LN(x1)
    ln_kernel<false><<<MROWS, 256>>>(x1, g2, b2, xn);
    // 8. h = gelu(xn @ W1 + bm1)
    gemm_tf32<<<dim3(MLPH/128, MROWS/128), 256>>>(xn, W1, hbuf, MROWS, MLPH, Cc);
    {
        size_t t4 = (size_t)MROWS*MLPH/4;
        epi_kernel<5><<<(unsigned)((t4 + 255)/256), 256>>>(hbuf, bm1, nullptr, MLPH/4, t4);
    }
    // 9. x2 = x1 + h @ W2 + bm2
    gemm_tf32<<<dim3(Cc/128, MROWS/128), 256>>>(hbuf, W2, x2, MROWS, Cc, MLPH);
    {
        size_t t4 = (size_t)MROWS*Cc/4;
        epi_kernel<3><<<(unsigned)((t4 + 255)/256), 256>>>(x2, bm2, x1, Cc/4, t4);
    }
    // 10. w_ts
    wts_kernel<<<Bb*LT, 256>>>();
    // 11. support = x2 @ Wg + bg
    gemm_tf32<<<dim3(Cc/128, MROWS/128), 256>>>(x2, Wg, sup, MROWS, Cc, Cc);
    {
        size_t t4 = (size_t)MROWS*Cc/4;
        epi_kernel<1><<<(unsigned)((t4 + 255)/256), 256>>>(sup, bg, nullptr, Cc/4, t4);
    }
    // 12. xg = adj @ support (block sparse)
    xg_top_kernel<<<Bb*LT, 256>>>();
    xg_bot_kernel<<<Bb*LS, 256>>>();
    // 13. out = xg + LN(xg)
    ln_kernel<true><<<MROWS, 256>>>(xg, g3, b3, out);
}

// round 3
// speedup vs baseline: 1.5049x; 1.0290x over previous
#include <cuda_runtime.h>
#include <mma.h>
#include <math.h>

using namespace nvcuda;

// Problem constants
#define Bb   32
#define Nn   320
#define Cc   768
#define Hh   12
#define HDd  64
#define MLPH 3072
#define LT   64
#define LS   256
#define MROWS (Bb*Nn)          // 10240
#define C3   (3*Cc)            // 2304
#define LNEPS 1e-5f

// ---------------- scratch ----------------------------------------------------
__device__ float g_xn  [(size_t)MROWS*Cc];
__device__ float g_qkv [(size_t)MROWS*C3];
__device__ float g_attn[(size_t)Bb*Hh*Nn*Nn];
__device__ float g_ctx [(size_t)MROWS*Cc];
__device__ float g_x1  [(size_t)MROWS*Cc];
__device__ float g_h   [(size_t)MROWS*MLPH];
__device__ float g_x2  [(size_t)MROWS*Cc];
__device__ float g_wts [(size_t)Bb*LT*LS];
__device__ float g_sup [(size_t)MROWS*Cc];
__device__ float g_xg  [(size_t)MROWS*Cc];
// pre-rounded (tf32) weights
#define WQKV_N  (Cc*C3)        // 1769472
#define WPROJ_N (Cc*Cc)        // 589824
#define W1_N    (Cc*MLPH)      // 2359296
#define W2_N    (MLPH*Cc)      // 2359296
#define WG_N    (Cc*Cc)        // 589824
__device__ float g_wbuf[(size_t)WQKV_N + WPROJ_N + W1_N + W2_N + WG_N];

// ---------------- helpers ----------------------------------------------------
__device__ __forceinline__ float to_tf32(float x) {
    asm("cvt.rna.tf32.f32 %0, %1;" : "=f"(x) : "f"(x));
    return x;
}
__device__ __forceinline__ unsigned smem_u32(const void* p) {
    return (unsigned)__cvta_generic_to_shared(p);
}
__device__ __forceinline__ void cp16(unsigned dst, const void* src) {
    asm volatile("cp.async.cg.shared.global [%0], [%1], 16;" :: "r"(dst), "l"(src));
}
__device__ __forceinline__ void cp_commit() {
    asm volatile("cp.async.commit_group;");
}
template<int N>
__device__ __forceinline__ void cp_wait() {
    asm volatile("cp.async.wait_group %0;" :: "n"(N));
}

// ---------------- round-to-tf32 copy (weights, once per launch) -------------
__global__ void tf32_round_copy(const float* __restrict__ s,
                                float* __restrict__ d, int n4) {
    const int i = blockIdx.x * blockDim.x + threadIdx.x;
    if (i >= n4) return;
    float4 v = ((const float4*)s)[i];
    v.x = to_tf32(v.x); v.y = to_tf32(v.y);
    v.z = to_tf32(v.z); v.w = to_tf32(v.w);
    ((float4*)d)[i] = v;
}

// ---------------- LayerNorm ---------------------------------------------------
template<bool ADDX, bool ROUND>
__global__ void ln_kernel(const float* __restrict__ x,
                          const float* __restrict__ g,
                          const float* __restrict__ b,
                          float* __restrict__ out) {
    const int row = blockIdx.x;
    const float* xr = x + (size_t)row * Cc;
    float v[3];
    float s = 0.f, sq = 0.f;
#pragma unroll
    for (int j = 0; j < 3; j++) {
        v[j] = xr[threadIdx.x + j*256];
        s += v[j]; sq += v[j]*v[j];
    }
#pragma unroll
    for (int o = 16; o > 0; o >>= 1) {
        s  += __shfl_xor_sync(0xffffffffu, s,  o);
        sq += __shfl_xor_sync(0xffffffffu, sq, o);
    }
    __shared__ float ss[8], ssq[8];
    __shared__ float bm, brs;
    const int w = threadIdx.x >> 5;
    if ((threadIdx.x & 31) == 0) { ss[w] = s; ssq[w] = sq; }
    __syncthreads();
    if (threadIdx.x == 0) {
        float a = 0.f, aq = 0.f;
#pragma unroll
        for (int i = 0; i < 8; i++) { a += ss[i]; aq += ssq[i]; }
        const float m = a * (1.f/Cc);
        bm  = m;
        brs = rsqrtf(aq * (1.f/Cc) - m*m + LNEPS);
    }
    __syncthreads();
    const float m = bm, rs = brs;
    float* outr = out + (size_t)row * Cc;
#pragma unroll
    for (int j = 0; j < 3; j++) {
        const int c = threadIdx.x + j*256;
        float r = (v[j] - m) * rs * g[c] + b[c];
        if (ADDX)  r += v[j];
        if (ROUND) r = to_tf32(r);
        outr[c] = r;
    }
}

// ---------------- TF32 tensor-core GEMM 128x128x32, cp.async 2-stage --------
// EPI bit0: +bias  bit1: +res  bit2: gelu  bit3: round output to tf32
// All A / W inputs must already be tf32-rounded.
#define AS_LD    36
#define BS_LD    132
#define A_STAGE  (128*AS_LD)   // 4608 floats
#define B_STAGE  (32*BS_LD)    // 4224 floats
#define GEMM_SMEM_FLOATS (2*A_STAGE + 2*B_STAGE)   // 17664
#define GEMM_SMEM_BYTES  (GEMM_SMEM_FLOATS*4)      // 70656

template<int EPI>
__global__ void __launch_bounds__(256, 2)
gemm_tc(const float* __restrict__ A, const float* __restrict__ W,
        const float* __restrict__ bias, const float* __restrict__ res,
        float* __restrict__ Cout, int M, int Nd, int K) {
    extern __shared__ float smem_f[];
    float* As_base = smem_f;
    float* Bs_base = smem_f + 2*A_STAGE;

    const int t    = threadIdx.x;
    const int warp = t >> 5;
    const int wm   = (warp >> 2) * 64;   // 0 or 64
    const int wn   = (warp & 3) * 32;    // 0,32,64,96
    const int m0   = blockIdx.y * 128, n0 = blockIdx.x * 128;

    wmma::fragment<wmma::accumulator, 16, 16, 8, float> acc[4][2];
#pragma unroll
    for (int i = 0; i < 4; i++)
#pragma unroll
        for (int j = 0; j < 2; j++) wmma::fill_fragment(acc[i][j], 0.f);

    // load one k-stage (BK=32) into stage buffers
    auto load_stage = [&](int stage, int kt) {
        float* as = As_base + stage*A_STAGE;
        float* bs = Bs_base + stage*B_STAGE;
#pragma unroll
        for (int p = 0; p < 4; p++) {
            const int c  = t + 256*p;
            const int ar = c >> 3, akc = (c & 7) * 4;
            cp16(smem_u32(as + ar*AS_LD + akc),
                 A + (size_t)(m0 + ar) * K + kt + akc);
        }
#pragma unroll
        for (int p = 0; p < 4; p++) {
            const int c  = t + 256*p;
            const int bk = c >> 5, bnc = (c & 31) * 4;
            cp16(smem_u32(bs + bk*BS_LD + bnc),
                 W + (size_t)(kt + bk) * Nd + n0 + bnc);
        }
        cp_commit();
    };

    load_stage(0, 0);

    const int niter = K / 32;
    for (int it = 0; it < niter; it++) {
        const int cur = it & 1;
        if (it + 1 < niter) {
            load_stage(cur ^ 1, (it + 1) * 32);
            cp_wait<1>();
        } else {
            cp_wait<0>();
        }
        __syncthreads();

        const float* as = As_base + cur*A_STAGE;
        const float* bs = Bs_base + cur*B_STAGE;
#pragma unroll
        for (int kk = 0; kk < 4; kk++) {
            const int k8 = kk * 8;
            wmma::fragment<wmma::matrix_a, 16, 16, 8, wmma::precision::tf32, wmma::row_major> a[4];
            wmma::fragment<wmma::matrix_b, 16, 16, 8, wmma::precision::tf32, wmma::row_major> bf[2];
#pragma unroll
            for (int i = 0; i < 4; i++)
                wmma::load_matrix_sync(a[i], as + (wm + i*16)*AS_LD + k8, AS_LD);
#pragma unroll
            for (int j = 0; j < 2; j++)
                wmma::load_matrix_sync(bf[j], bs + k8*BS_LD + wn + j*16, BS_LD);
#pragma unroll
            for (int i = 0; i < 4; i++)
#pragma unroll
                for (int j = 0; j < 2; j++)
                    wmma::mma_sync(acc[i][j], a[i], bf[j], acc[i][j]);
        }
        __syncthreads();
    }

    // epilogue via smem transpose: Cs[128][128] (64KB, fits in the 70.6KB)
    float* Cs = smem_f;
#pragma unroll
    for (int i = 0; i < 4; i++)
#pragma unroll
        for (int j = 0; j < 2; j++)
            wmma::store_matrix_sync(Cs + (size_t)(wm + i*16)*128 + wn + j*16,
                                    acc[i][j], 128, wmma::mem_row_major);
    __syncthreads();

#pragma unroll
    for (int p = 0; p < 16; p++) {
        const int chunk = t + 256*p;          // 4096 float4 chunks
        const int row = chunk >> 5;
        const int col = (chunk & 31) * 4;
        float4 v = ((const float4*)Cs)[chunk];
        if (EPI & 1) {
            const float4 bb = *(const float4*)(bias + n0 + col);
            v.x += bb.x; v.y += bb.y; v.z += bb.z; v.w += bb.w;
        }
        if (EPI & 4) {
            v.x = 0.5f*v.x*(1.f + erff(v.x*0.70710678118654752f));
            v.y = 0.5f*v.y*(1.f + erff(v.y*0.70710678118654752f));
            v.z = 0.5f*v.z*(1.f + erff(v.z*0.70710678118654752f));
            v.w = 0.5f*v.w*(1.f + erff(v.w*0.70710678118654752f));
        }
        if (EPI & 2) {
            const float4 r = *(const float4*)(res + (size_t)(m0 + row)*Nd + n0 + col);
            v.x += r.x; v.y += r.y; v.z += r.z; v.w += r.w;
        }
        if (EPI & 8) {
            v.x = to_tf32(v.x); v.y = to_tf32(v.y);
            v.z = to_tf32(v.z); v.w = to_tf32(v.w);
        }
        *(float4*)(Cout + (size_t)(m0 + row)*Nd + n0 + col) = v;
    }
}

// ---------------- attention logits (tf32 wmma, pre-rounded inputs) ----------
__global__ void __launch_bounds__(256)
logits_wmma() {
    __shared__ float Qs[64][68];
    __shared__ float Ks[64][68];
    const int bh = blockIdx.z;
    const int b = bh / Hh, h = bh % Hh;
    const int n0 = blockIdx.x * 64, m0 = blockIdx.y * 64;
    const int t = threadIdx.x;
    for (int idx = t; idx < 4096; idx += 256) {
        const int r = idx >> 6, d = idx & 63;
        Qs[r][d] = g_qkv[(size_t)(b*Nn + n0 + r)*C3 + 0*Cc + h*HDd + d];
        Ks[r][d] = g_qkv[(size_t)(b*Nn + m0 + r)*C3 + 1*Cc + h*HDd + d];
    }
    __syncthreads();
    const int warp = t >> 5;
    const int wm = (warp >> 2) * 32;
    const int wn = (warp & 3) * 16;
    wmma::fragment<wmma::accumulator, 16, 16, 8, float> acc[2];
    wmma::fill_fragment(acc[0], 0.f);
    wmma::fill_fragment(acc[1], 0.f);
#pragma unroll
    for (int k8 = 0; k8 < 64; k8 += 8) {
        wmma::fragment<wmma::matrix_a, 16, 16, 8, wmma::precision::tf32, wmma::row_major> a[2];
        wmma::fragment<wmma::matrix_b, 16, 16, 8, wmma::precision::tf32, wmma::col_major> bf;
        wmma::load_matrix_sync(a[0], &Qs[wm][k8], 68);
        wmma::load_matrix_sync(a[1], &Qs[wm + 16][k8], 68);
        wmma::load_matrix_sync(bf, &Ks[wn][k8], 68);
        wmma::mma_sync(acc[0], a[0], bf, acc[0]);
        wmma::mma_sync(acc[1], a[1], bf, acc[1]);
    }
#pragma unroll
    for (int i = 0; i < 2; i++) {
#pragma unroll
        for (int e = 0; e < acc[i].num_elements; e++) acc[i].x[e] *= 0.125f;
        wmma::store_matrix_sync(g_attn + ((size_t)bh*Nn + n0 + wm + i*16)*Nn + m0 + wn,
                                acc[i], Nn, wmma::mem_row_major);
    }
}

// ---------------- softmax: one warp per row (len 320), tf32-rounded out -----
__global__ void softmax_warp() {
    const int row  = blockIdx.x * 8 + (threadIdx.x >> 5);
    const int lane = threadIdx.x & 31;
    float* p = g_attn + (size_t)row * Nn;
    float v[10];
    float m = -1e30f;
#pragma unroll
    for (int i = 0; i < 10; i++) { v[i] = p[lane + 32*i]; m = fmaxf(m, v[i]); }
#pragma unroll
    for (int o = 16; o > 0; o >>= 1) m = fmaxf(m, __shfl_xor_sync(0xffffffffu, m, o));
    float s = 0.f;
#pragma unroll
    for (int i = 0; i < 10; i++) { v[i] = expf(v[i] - m); s += v[i]; }
#pragma unroll
    for (int o = 16; o > 0; o >>= 1) s += __shfl_xor_sync(0xffffffffu, s, o);
    const float inv = 1.f / s;
#pragma unroll
    for (int i = 0; i < 10; i++) p[lane + 32*i] = to_tf32(v[i] * inv);
}

// ---------------- ctx = attn @ v (tf32 wmma, rounded output) ----------------
__global__ void __launch_bounds__(256)
ctx_wmma() {
    __shared__ float As[64][68];
    __shared__ float Vs[64][68];
    const int bh = blockIdx.y;
    const int b = bh / Hh, h = bh % Hh;
    const int n0 = blockIdx.x * 64;
    const int t = threadIdx.x;
    const int warp = t >> 5;
    const int wm = (warp >> 2) * 32;
    const int wn = (warp & 3) * 16;
    wmma::fragment<wmma::accumulator, 16, 16, 8, float> acc[2];
    wmma::fill_fragment(acc[0], 0.f);
    wmma::fill_fragment(acc[1], 0.f);
    for (int m0 = 0; m0 < Nn; m0 += 64) {
        for (int idx = t; idx < 4096; idx += 256) {
            const int r = idx >> 6, c = idx & 63;
            As[r][c] = g_attn[((size_t)bh*Nn + n0 + r)*Nn + m0 + c];
            Vs[r][c] = g_qkv[(size_t)(b*Nn + m0 + r)*C3 + 2*Cc + h*HDd + c];
        }
        __syncthreads();
#pragma unroll
        for (int k8 = 0; k8 < 64; k8 += 8) {
            wmma::fragment<wmma::matrix_a, 16, 16, 8, wmma::precision::tf32, wmma::row_major> a[2];
            wmma::fragment<wmma::matrix_b, 16, 16, 8, wmma::precision::tf32, wmma::row_major> bf;
            wmma::load_matrix_sync(a[0], &As[wm][k8], 68);
            wmma::load_matrix_sync(a[1], &As[wm + 16][k8], 68);
            wmma::load_matrix_sync(bf, &Vs[k8][wn], 68);
            wmma::mma_sync(acc[0], a[0], bf, acc[0]);
            wmma::mma_sync(acc[1], a[1], bf, acc[1]);
        }
        __syncthreads();
    }
#pragma unroll
    for (int i = 0; i < 2; i++) {
#pragma unroll
        for (int e = 0; e < acc[i].num_elements; e++)
            acc[i].x[e] = to_tf32(acc[i].x[e]);
        wmma::store_matrix_sync(g_ctx + (size_t)(b*Nn + n0 + wm + i*16)*Cc + h*HDd + wn,
                                acc[i], Cc, wmma::mem_row_major);
    }
}

// ---------------- w_ts: head-mean of attn[:, :, :LT, LT:], softmax over s ---
__global__ void wts_kernel() {
    const int b  = blockIdx.x / LT;
    const int tq = blockIdx.x % LT;
    const int s  = threadIdx.x;
    float a = 0.f;
#pragma unroll
    for (int h = 0; h < Hh; h++)
        a += g_attn[((size_t)(b*Hh + h)*Nn + tq)*Nn + LT + s];
    a *= (1.f / Hh);
    __shared__ float rbuf[8];
    __shared__ float bmax, bsum;
    float m = a;
#pragma unroll
    for (int o = 16; o > 0; o >>= 1) m = fmaxf(m, __shfl_xor_sync(0xffffffffu, m, o));
    if ((s & 31) == 0) rbuf[s >> 5] = m;
    __syncthreads();
    if (s < 32) {
        float mm = (s < 8) ? rbuf[s] : -1e30f;
#pragma unroll
        for (int o = 4; o > 0; o >>= 1) mm = fmaxf(mm, __shfl_xor_sync(0xffffffffu, mm, o));
        if (s == 0) bmax = mm;
    }
    __syncthreads();
    const float e = expf(a - bmax);
    float su = e;
#pragma unroll
    for (int o = 16; o > 0; o >>= 1) su += __shfl_xor_sync(0xffffffffu, su, o);
    __syncthreads();
    if ((s & 31) == 0) rbuf[s >> 5] = su;
    __syncthreads();
    if (s < 32) {
        float ss = (s < 8) ? rbuf[s] : 0.f;
#pragma unroll
        for (int o = 4; o > 0; o >>= 1) ss += __shfl_xor_sync(0xffffffffu, ss, o);
        if (s == 0) bsum = ss;
    }
    __syncthreads();
    g_wts[((size_t)b*LT + tq)*LS + s] = e / bsum;
}

// ---------------- graph conv (block-sparse adj) -----------------------------
__global__ void xg_top_kernel() {
    const int b  = blockIdx.x / LT;
    const int tq = blockIdx.x % LT;
    __shared__ float w[LS];
    w[threadIdx.x] = g_wts[((size_t)b*LT + tq)*LS + threadIdx.x];
    __syncthreads();
    float a0 = 0.f, a1 = 0.f, a2 = 0.f;
    const float* base = g_sup + (size_t)(b*Nn + LT)*Cc + threadIdx.x;
    for (int s = 0; s < LS; s++) {
        const float ws = w[s];
        const float* sup = base + (size_t)s*Cc;
        a0 += ws * sup[0];
        a1 += ws * sup[256];
        a2 += ws * sup[512];
    }
    float* o = g_xg + (size_t)(b*Nn + tq)*Cc + threadIdx.x;
    o[0] = a0; o[256] = a1; o[512] = a2;
}
__global__ void xg_bot_kernel() {
    const int b = blockIdx.x / LS;
    const int s = blockIdx.x % LS;
    __shared__ float w[LT];
    if (threadIdx.x < LT)
        w[threadIdx.x] = g_wts[((size_t)b*LT + threadIdx.x)*LS + s];
    __syncthreads();
    float a0 = 0.f, a1 = 0.f, a2 = 0.f;
    const float* base = g_sup + (size_t)(b*Nn)*Cc + threadIdx.x;
    for (int tq = 0; tq < LT; tq++) {
        const float wt = w[tq];
        const float* sup = base + (size_t)tq*Cc;
        a0 += wt * sup[0];
        a1 += wt * sup[256];
        a2 += wt * sup[512];
    }
    float* o = g_xg + (size_t)(b*Nn + LT + s)*Cc + threadIdx.x;
    o[0] = a0; o[256] = a1; o[512] = a2;
}

// ---------------------------------------------------------------------------
extern "C" void kernel_launch(void* const* d_in, const int* in_sizes, int n_in,
                              void* d_out, int out_size) {
    const float* x     = (const float*)d_in[0];
    const float* g1    = (const float*)d_in[3];
    const float* b1    = (const float*)d_in[4];
    const float* Wqkv  = (const float*)d_in[5];
    const float* Wproj = (const float*)d_in[6];
    const float* bproj = (const float*)d_in[7];
    const float* g2    = (const float*)d_in[8];
    const float* b2    = (const float*)d_in[9];
    const float* W1    = (const float*)d_in[10];
    const float* bm1   = (const float*)d_in[11];
    const float* W2    = (const float*)d_in[12];
    const float* bm2   = (const float*)d_in[13];
    const float* Wg    = (const float*)d_in[14];
    const float* bg    = (const float*)d_in[15];
    const float* g3    = (const float*)d_in[16];
    const float* b3    = (const float*)d_in[17];
    float* out = (float*)d_out;

    float *xn, *qkv, *ctx, *x1, *hbuf, *x2, *sup, *xg, *wbuf;
    cudaGetSymbolAddress((void**)&xn,   g_xn);
    cudaGetSymbolAddress((void**)&qkv,  g_qkv);
    cudaGetSymbolAddress((void**)&ctx,  g_ctx);
    cudaGetSymbolAddress((void**)&x1,   g_x1);
    cudaGetSymbolAddress((void**)&hbuf, g_h);
    cudaGetSymbolAddress((void**)&x2,   g_x2);
    cudaGetSymbolAddress((void**)&sup,  g_sup);
    cudaGetSymbolAddress((void**)&xg,   g_xg);
    cudaGetSymbolAddress((void**)&wbuf, g_wbuf);

    float* wqkv_r  = wbuf;
    float* wproj_r = wqkv_r  + WQKV_N;
    float* w1_r    = wproj_r + WPROJ_N;
    float* w2_r    = w1_r    + W1_N;
    float* wg_r    = w2_r    + W2_N;

    // allow >48KB dynamic smem for GEMM instantiations (idempotent)
    cudaFuncSetAttribute(gemm_tc<8>,  cudaFuncAttributeMaxDynamicSharedMemorySize, GEMM_SMEM_BYTES);
    cudaFuncSetAttribute(gemm_tc<3>,  cudaFuncAttributeMaxDynamicSharedMemorySize, GEMM_SMEM_BYTES);
    cudaFuncSetAttribute(gemm_tc<13>, cudaFuncAttributeMaxDynamicSharedMemorySize, GEMM_SMEM_BYTES);
    cudaFuncSetAttribute(gemm_tc<11>, cudaFuncAttributeMaxDynamicSharedMemorySize, GEMM_SMEM_BYTES);
    cudaFuncSetAttribute(gemm_tc<1>,  cudaFuncAttributeMaxDynamicSharedMemorySize, GEMM_SMEM_BYTES);

    // 0. pre-round weights to tf32 (deterministic, every call)
    tf32_round_copy<<<(WQKV_N/4 + 255)/256, 256>>>(Wqkv,  wqkv_r,  WQKV_N/4);
    tf32_round_copy<<<(WPROJ_N/4 + 255)/256, 256>>>(Wproj, wproj_r, WPROJ_N/4);
    tf32_round_copy<<<(W1_N/4 + 255)/256, 256>>>(W1, w1_r, W1_N/4);
    tf32_round_copy<<<(W2_N/4 + 255)/256, 256>>>(W2, w2_r, W2_N/4);
    tf32_round_copy<<<(WG_N/4 + 255)/256, 256>>>(Wg, wg_r, WG_N/4);

    // 1. xn = round(LN(x))
    ln_kernel<false, true><<<MROWS, 256>>>(x, g1, b1, xn);
    // 2. qkv = round(xn @ Wqkv)
    gemm_tc<8><<<dim3(C3/128, MROWS/128), 256, GEMM_SMEM_BYTES>>>(
        xn, wqkv_r, nullptr, nullptr, qkv, MROWS, C3, Cc);
    // 3. logits
    logits_wmma<<<dim3(Nn/64, Nn/64, Bb*Hh), 256>>>();
    // 4. softmax (rounded probs)
    softmax_warp<<<Bb*Hh*Nn/8, 256>>>();
    // 5. ctx = round(attn @ v)
    ctx_wmma<<<dim3(Nn/64, Bb*Hh), 256>>>();
    // 6. x1 = x + ctx @ Wproj + bproj   (full fp32 residual stream)
    gemm_tc<3><<<dim3(Cc/128, MROWS/128), 256, GEMM_SMEM_BYTES>>>(
        ctx, wproj_r, bproj, x, x1, MROWS, Cc, Cc);
    // 7. xn = round(LN(x1))
    ln_kernel<false, true><<<MROWS, 256>>>(x1, g2, b2, xn);
    // 8. h = round(gelu(xn @ W1 + bm1))
    gemm_tc<13><<<dim3(MLPH/128, MROWS/128), 256, GEMM_SMEM_BYTES>>>(
        xn, w1_r, bm1, nullptr, hbuf, MROWS, MLPH, Cc);
    // 9. x2 = round(x1 + h @ W2 + bm2)   (x2 only feeds the Wg GEMM)
    gemm_tc<11><<<dim3(Cc/128, MROWS/128), 256, GEMM_SMEM_BYTES>>>(
        hbuf, w2_r, bm2, x1, x2, MROWS, Cc, MLPH);
    // 10. w_ts
    wts_kernel<<<Bb*LT, 256>>>();
    // 11. support = x2 @ Wg + bg  (fp32 out)
    gemm_tc<1><<<dim3(Cc/128, MROWS/128), 256, GEMM_SMEM_BYTES>>>(
        x2, wg_r, bg, nullptr, sup, MROWS, Cc, Cc);
    // 12. xg = adj @ support (block sparse)
    xg_top_kernel<<<Bb*LT, 256>>>();
    xg_bot_kernel<<<Bb*LS, 256>>>();
    // 13. out = xg + LN(xg)
    ln_kernel<true, false><<<MROWS, 256>>>(xg, g3, b3, out);
}

// round 5
// speedup vs baseline: 3.6811x; 2.4461x over previous
#include <cuda_runtime.h>
#include <mma.h>
#include <math.h>
#include <stdint.h>

using namespace nvcuda;

// Problem constants
#define Bb   32
#define Nn   320
#define Cc   768
#define Hh   12
#define HDd  64
#define MLPH 3072
#define LT   64
#define LS   256
#define MROWS (Bb*Nn)          // 10240
#define C3   (3*Cc)            // 2304
#define LNEPS 1e-5f

// tcgen05 only exists in arch-specific (sm_103a / sm_100a) device passes.
#if defined(__CUDA_ARCH__) && (defined(__CUDA_ARCH_FEAT_SM103_ALL) || defined(__CUDA_ARCH_FEAT_SM100_ALL) || defined(__CUDA_ARCH_FEAT_SM101_ALL))
#define TC5 1
#else
#define TC5 0
#endif

// ---------------- scratch ----------------------------------------------------
__device__ float g_xn  [(size_t)MROWS*Cc];
__device__ float g_qkv [(size_t)MROWS*C3];
__device__ float g_attn[(size_t)Bb*Hh*Nn*Nn];
__device__ float g_ctx [(size_t)MROWS*Cc];
__device__ float g_x1  [(size_t)MROWS*Cc];
__device__ float g_h   [(size_t)MROWS*MLPH];
__device__ float g_x2  [(size_t)MROWS*Cc];
__device__ float g_wts [(size_t)Bb*LT*LS];
__device__ float g_sup [(size_t)MROWS*Cc];
__device__ float g_xg  [(size_t)MROWS*Cc];
// transposed + tf32-rounded weights (W^T, [Nd][K] row-major)
#define WQKV_N  (Cc*C3)
#define WPROJ_N (Cc*Cc)
#define W1_N    (Cc*MLPH)
#define W2_N    (MLPH*Cc)
#define WG_N    (Cc*Cc)
__device__ float g_wbuf[(size_t)WQKV_N + WPROJ_N + W1_N + W2_N + WG_N];

// ---------------- helpers ----------------------------------------------------
__device__ __forceinline__ float to_tf32(float x) {
    asm("cvt.rna.tf32.f32 %0, %1;" : "=f"(x) : "f"(x));
    return x;
}
__device__ __forceinline__ unsigned smem_u32(const void* p) {
    return (unsigned)__cvta_generic_to_shared(p);
}
__device__ __forceinline__ void cp16(unsigned dst, const void* src) {
    asm volatile("cp.async.cg.shared.global [%0], [%1], 16;" :: "r"(dst), "l"(src));
}
__device__ __forceinline__ void cp_commit() {
    asm volatile("cp.async.commit_group;");
}
template<int N>
__device__ __forceinline__ void cp_wait() {
    asm volatile("cp.async.wait_group %0;" :: "n"(N));
}
#define SWZ(off) ((off) ^ (((off) >> 3) & 0x70))

#if TC5
__device__ __forceinline__ uint32_t elect_one() {
    uint32_t pred;
    asm volatile("{\n\t.reg .pred p;\n\telect.sync _|p, 0xFFFFFFFF;\n\t"
                 "selp.b32 %0, 1, 0, p;\n\t}" : "=r"(pred));
    return pred;
}
__device__ __forceinline__ void mbar_wait(uint32_t mbar, uint32_t parity) {
    asm volatile(
        "{\n\t.reg .pred P;\n"
        "MBW_%=:\n\t"
        "mbarrier.try_wait.parity.shared.b64 P, [%0], %1;\n\t"
        "@!P bra MBW_%=;\n\t}"
        :: "r"(mbar), "r"(parity) : "memory");
}
static __device__ __forceinline__ uint64_t smem_desc_sw128(uint32_t addr) {
    const uint64_t base =
        (uint64_t(2)  << 61) | (uint64_t(1) << 46) |
        (uint64_t(64) << 32) | (uint64_t(1) << 16);
    return base | ((uint64_t)(addr >> 4) & 0x3FFF);
}
// idesc kind::tf32: dtype f32(1)@[4:5], atype tf32(2)@[7:9], btype tf32(2)@[10:12],
// N/8=16@[17:22], M/16=8@[24:28]
#define IDESC_TF32 ((1u<<4) | (2u<<7) | (2u<<10) | (16u<<17) | (8u<<24))
__device__ __forceinline__ void mma_tf32_ss(uint32_t d, uint64_t ad, uint64_t bd,
                                            uint32_t en) {
    asm volatile(
        "{\n\t.reg .pred p;\n\t"
        "setp.ne.u32 p, %4, 0;\n\t"
        "tcgen05.mma.cta_group::1.kind::tf32 [%0], %1, %2, %3, {%5, %5, %5, %5}, p;\n\t}"
        :: "r"(d), "l"(ad), "l"(bd), "r"((uint32_t)IDESC_TF32), "r"(en), "r"(0u)
        : "memory");
}
#endif

// ---------------- weight prep: WT[n][k] = tf32(W[k][n]) ---------------------
__global__ void wprep(const float* __restrict__ W, float* __restrict__ WT,
                      int K, int Nd) {
    __shared__ float tile[32][33];
    const int kb = blockIdx.y * 32, nb = blockIdx.x * 32;
    const int tx = threadIdx.x;
#pragma unroll
    for (int i = threadIdx.y; i < 32; i += 8)
        tile[i][tx] = W[(size_t)(kb + i) * Nd + nb + tx];
    __syncthreads();
#pragma unroll
    for (int i = threadIdx.y; i < 32; i += 8)
        WT[(size_t)(nb + i) * K + kb + tx] = to_tf32(tile[tx][i]);
}

// ---------------- LayerNorm ---------------------------------------------------
template<bool ADDX, bool ROUND>
__global__ void ln_kernel(const float* __restrict__ x,
                          const float* __restrict__ g,
                          const float* __restrict__ b,
                          float* __restrict__ out) {
    const int row = blockIdx.x;
    const float* xr = x + (size_t)row * Cc;
    float v[3];
    float s = 0.f, sq = 0.f;
#pragma unroll
    for (int j = 0; j < 3; j++) {
        v[j] = xr[threadIdx.x + j*256];
        s += v[j]; sq += v[j]*v[j];
    }
#pragma unroll
    for (int o = 16; o > 0; o >>= 1) {
        s  += __shfl_xor_sync(0xffffffffu, s,  o);
        sq += __shfl_xor_sync(0xffffffffu, sq, o);
    }
    __shared__ float ss[8], ssq[8];
    __shared__ float bm, brs;
    const int w = threadIdx.x >> 5;
    if ((threadIdx.x & 31) == 0) { ss[w] = s; ssq[w] = sq; }
    __syncthreads();
    if (threadIdx.x == 0) {
        float a = 0.f, aq = 0.f;
#pragma unroll
        for (int i = 0; i < 8; i++) { a += ss[i]; aq += ssq[i]; }
        const float m = a * (1.f/Cc);
        bm  = m;
        brs = rsqrtf(aq * (1.f/Cc) - m*m + LNEPS);
    }
    __syncthreads();
    const float m = bm, rs = brs;
    float* outr = out + (size_t)row * Cc;
#pragma unroll
    for (int j = 0; j < 3; j++) {
        const int c = threadIdx.x + j*256;
        float r = (v[j] - m) * rs * g[c] + b[c];
        if (ADDX)  r += v[j];
        if (ROUND) r = to_tf32(r);
        outr[c] = r;
    }
}

// ---------------- unified GEMM: A[M,K] @ WT[Nd,K]^T, 128x128 tile, BK=32 ----
// EPI bit0: +bias  bit1: +res  bit2: gelu  bit3: round output to tf32
// Both operands pre-rounded to tf32. 256 threads.
#define GT_TILE   16384                     // 128 rows * 128 B (tcgen05 tiles)
#define FB_STAGE  (128*36)                  // fallback stage: [128][36] floats
#define GEMM_SMEM (4*FB_STAGE*4)            // 73728 B (covers both paths)

template<int EPI>
__global__ void __launch_bounds__(256)
gemm_tc(const float* __restrict__ A, const float* __restrict__ WT,
        const float* __restrict__ bias, const float* __restrict__ res,
        float* __restrict__ Cout, int M, int Nd, int K) {
    extern __shared__ float smem_f[];
    const int t   = threadIdx.x;
    const int wid = t >> 5;
    const int lid = t & 31;
    const int m0  = blockIdx.y * 128, n0 = blockIdx.x * 128;

#if TC5
    // ======================= tcgen05 SS tf32 path ===========================
    const uint32_t raw  = smem_u32(smem_f);
    const uint32_t base = (raw + 1023u) & ~1023u;   // 1KB align for SW128

    __shared__ uint32_t s_tmem;
    __shared__ uint64_t s_mbar;
    const uint32_t mbar_a = smem_u32(&s_mbar);

    if (wid == 0) {
        asm volatile("tcgen05.alloc.cta_group::1.sync.aligned.shared::cta.b32 [%0], 128;"
                     :: "r"(smem_u32(&s_tmem)) : "memory");
        asm volatile("tcgen05.relinquish_alloc_permit.cta_group::1.sync.aligned;");
    }
    if (t == 0)
        asm volatile("mbarrier.init.shared.b64 [%0], 1;" :: "r"(mbar_a) : "memory");
    __syncthreads();
    uint32_t tmem;
    asm volatile("ld.shared.b32 %0, [%1];" : "=r"(tmem) : "r"(smem_u32(&s_tmem)));

    const uint32_t sa[2] = { base,             base + GT_TILE };
    const uint32_t sb[2] = { base + 2*GT_TILE, base + 3*GT_TILE };

    auto load_stage = [&](int st, int kt) {
#pragma unroll
        for (int p = 0; p < 4; p++) {              // A: 1024 x 16B / 256 thr
            const int c   = t + 256*p;
            const int row = c >> 3, cc = c & 7;
            cp16(sa[st] + SWZ(row*128 + cc*16),
                 A + (size_t)(m0 + row) * K + kt + cc*4);
        }
#pragma unroll
        for (int p = 0; p < 4; p++) {              // B: WT rows n0..n0+127
            const int c   = t + 256*p;
            const int row = c >> 3, cc = c & 7;
            cp16(sb[st] + SWZ(row*128 + cc*16),
                 WT + (size_t)(n0 + row) * K + kt + cc*4);
        }
        cp_commit();
    };

    uint32_t ep = 0;
    if (wid == 0) ep = elect_one();

    const int nk = K / 32;
    load_stage(0, 0);

    for (int it = 0; it < nk; it++) {
        const int cur = it & 1;
        if (it + 1 < nk) { load_stage(cur ^ 1, (it + 1) * 32); cp_wait<1>(); }
        else             { cp_wait<0>(); }
        asm volatile("fence.proxy.async.shared::cta;" ::: "memory");
        __syncthreads();

        if (wid == 0 && ep) {
            const uint64_t ad = smem_desc_sw128(sa[cur]);
            const uint64_t bd = smem_desc_sw128(sb[cur]);
#pragma unroll
            for (int ks = 0; ks < 4; ks++)         // 4 x K=8 dispatches
                mma_tf32_ss(tmem, ad + 2*ks, bd + 2*ks,
                            (uint32_t)((it > 0) | (ks > 0)));
            asm volatile(
                "tcgen05.commit.cta_group::1.mbarrier::arrive::one.shared::cluster.b64 [%0];"
                :: "r"(mbar_a) : "memory");
        }
        mbar_wait(mbar_a, it & 1);
    }

    asm volatile("tcgen05.fence::after_thread_sync;" ::: "memory");

    // epilogue: warps 0-3 -> cols [0,64), warps 4-7 -> cols [64,128)
    const int sp    = wid & 3;
    const int row   = m0 + sp*32 + lid;
    const int cbase = (wid >> 2) * 64;
#pragma unroll
    for (int cb = 0; cb < 64; cb += 32) {
        uint32_t dr[32];
        asm volatile(
            "tcgen05.ld.sync.aligned.32x32b.x32.b32 "
            "{%0, %1, %2, %3, %4, %5, %6, %7, "
            " %8, %9, %10, %11, %12, %13, %14, %15, "
            " %16, %17, %18, %19, %20, %21, %22, %23, "
            " %24, %25, %26, %27, %28, %29, %30, %31}, [%32];"
            : "=r"(dr[0]),  "=r"(dr[1]),  "=r"(dr[2]),  "=r"(dr[3]),
              "=r"(dr[4]),  "=r"(dr[5]),  "=r"(dr[6]),  "=r"(dr[7]),
              "=r"(dr[8]),  "=r"(dr[9]),  "=r"(dr[10]), "=r"(dr[11]),
              "=r"(dr[12]), "=r"(dr[13]), "=r"(dr[14]), "=r"(dr[15]),
              "=r"(dr[16]), "=r"(dr[17]), "=r"(dr[18]), "=r"(dr[19]),
              "=r"(dr[20]), "=r"(dr[21]), "=r"(dr[22]), "=r"(dr[23]),
              "=r"(dr[24]), "=r"(dr[25]), "=r"(dr[26]), "=r"(dr[27]),
              "=r"(dr[28]), "=r"(dr[29]), "=r"(dr[30]), "=r"(dr[31])
            : "r"(tmem + cbase + cb));
        asm volatile("tcgen05.wait::ld.sync.aligned;" ::: "memory");
#pragma unroll
        for (int j = 0; j < 32; j += 4) {
            const int col = n0 + cbase + cb + j;
            float4 v = make_float4(__uint_as_float(dr[j+0]), __uint_as_float(dr[j+1]),
                                   __uint_as_float(dr[j+2]), __uint_as_float(dr[j+3]));
            if (EPI & 1) {
                const float4 bb = *(const float4*)(bias + col);
                v.x += bb.x; v.y += bb.y; v.z += bb.z; v.w += bb.w;
            }
            if (EPI & 4) {
                v.x = 0.5f*v.x*(1.f + erff(v.x*0.70710678118654752f));
                v.y = 0.5f*v.y*(1.f + erff(v.y*0.70710678118654752f));
                v.z = 0.5f*v.z*(1.f + erff(v.z*0.70710678118654752f));
                v.w = 0.5f*v.w*(1.f + erff(v.w*0.70710678118654752f));
            }
            if (EPI & 2) {
                const float4 r = *(const float4*)(res + (size_t)row*Nd + col);
                v.x += r.x; v.y += r.y; v.z += r.z; v.w += r.w;
            }
            if (EPI & 8) {
                v.x = to_tf32(v.x); v.y = to_tf32(v.y);
                v.z = to_tf32(v.z); v.w = to_tf32(v.w);
            }
            *(float4*)(Cout + (size_t)row*Nd + col) = v;
        }
    }
    asm volatile("tcgen05.fence::before_thread_sync;" ::: "memory");
    __syncthreads();
    if (t == 0)
        asm volatile("mbarrier.inval.shared.b64 [%0];" :: "r"(mbar_a) : "memory");
    if (wid == 0)
        asm volatile("tcgen05.dealloc.cta_group::1.sync.aligned.b32 %0, 128;"
                     :: "r"(tmem));
#else
    // ======================= wmma tf32 fallback =============================
    float* As_base = smem_f;                   // 2 stages [128][36]
    float* Bs_base = smem_f + 2*FB_STAGE;      // 2 stages [128][36] (WT rows)
    const int warp = wid;
    const int wm   = (warp >> 2) * 64;
    const int wn   = (warp & 3) * 32;

    wmma::fragment<wmma::accumulator, 16, 16, 8, float> acc[4][2];
#pragma unroll
    for (int i = 0; i < 4; i++)
#pragma unroll
        for (int j = 0; j < 2; j++) wmma::fill_fragment(acc[i][j], 0.f);

    auto load_stage = [&](int st, int kt) {
        float* as = As_base + st*FB_STAGE;
        float* bs = Bs_base + st*FB_STAGE;
#pragma unroll
        for (int p = 0; p < 4; p++) {
            const int c  = t + 256*p;
            const int r0 = c >> 3, cc = (c & 7) * 4;
            cp16(smem_u32(as + r0*36 + cc), A  + (size_t)(m0 + r0) * K + kt + cc);
        }
#pragma unroll
        for (int p = 0; p < 4; p++) {
            const int c  = t + 256*p;
            const int r0 = c >> 3, cc = (c & 7) * 4;
            cp16(smem_u32(bs + r0*36 + cc), WT + (size_t)(n0 + r0) * K + kt + cc);
        }
        cp_commit();
    };

    load_stage(0, 0);
    const int nk = K / 32;
    for (int it = 0; it < nk; it++) {
        const int cur = it & 1;
        if (it + 1 < nk) { load_stage(cur ^ 1, (it + 1) * 32); cp_wait<1>(); }
        else             { cp_wait<0>(); }
        __syncthreads();
        const float* as = As_base + cur*FB_STAGE;
        const float* bs = Bs_base + cur*FB_STAGE;
#pragma unroll
        for (int kk = 0; kk < 4; kk++) {
            const int k8 = kk * 8;
            wmma::fragment<wmma::matrix_a, 16, 16, 8, wmma::precision::tf32, wmma::row_major> a[4];
            wmma::fragment<wmma::matrix_b, 16, 16, 8, wmma::precision::tf32, wmma::col_major> bf[2];
#pragma unroll
            for (int i = 0; i < 4; i++)
                wmma::load_matrix_sync(a[i], as + (wm + i*16)*36 + k8, 36);
#pragma unroll
            for (int j = 0; j < 2; j++)
                wmma::load_matrix_sync(bf[j], bs + (wn + j*16)*36 + k8, 36);
#pragma unroll
            for (int i = 0; i < 4; i++)
#pragma unroll
                for (int j = 0; j < 2; j++)
                    wmma::mma_sync(acc[i][j], a[i], bf[j], acc[i][j]);
        }
        __syncthreads();
    }

    float* Cs = smem_f;   // 128*128 floats = 64KB <= 72KB
#pragma unroll
    for (int i = 0; i < 4; i++)
#pragma unroll
        for (int j = 0; j < 2; j++)
            wmma::store_matrix_sync(Cs + (size_t)(wm + i*16)*128 + wn + j*16,
                                    acc[i][j], 128, wmma::mem_row_major);
    __syncthreads();

#pragma unroll
    for (int p = 0; p < 16; p++) {
        const int chunk = t + 256*p;
        const int row = chunk >> 5;
        const int col = (chunk & 31) * 4;
        float4 v = ((const float4*)Cs)[chunk];
        if (EPI & 1) {
            const float4 bb = *(const float4*)(bias + n0 + col);
            v.x += bb.x; v.y += bb.y; v.z += bb.z; v.w += bb.w;
        }
        if (EPI & 4) {
            v.x = 0.5f*v.x*(1.f + erff(v.x*0.70710678118654752f));
            v.y = 0.5f*v.y*(1.f + erff(v.y*0.70710678118654752f));
            v.z = 0.5f*v.z*(1.f + erff(v.z*0.70710678118654752f));
            v.w = 0.5f*v.w*(1.f + erff(v.w*0.70710678118654752f));
        }
        if (EPI & 2) {
            const float4 r = *(const float4*)(res + (size_t)(m0 + row)*Nd + n0 + col);
            v.x += r.x; v.y += r.y; v.z += r.z; v.w += r.w;
        }
        if (EPI & 8) {
            v.x = to_tf32(v.x); v.y = to_tf32(v.y);
            v.z = to_tf32(v.z); v.w = to_tf32(v.w);
        }
        *(float4*)(Cout + (size_t)(m0 + row)*Nd + n0 + col) = v;
    }
#endif
}

// ---------------- attention logits (tf32 wmma, pre-rounded inputs) ----------
__global__ void __launch_bounds__(256)
logits_wmma() {
    __shared__ float Qs[64][68];
    __shared__ float Ks[64][68];
    const int bh = blockIdx.z;
    const int b = bh / Hh, h = bh % Hh;
    const int n0 = blockIdx.x * 64, m0 = blockIdx.y * 64;
    const int t = threadIdx.x;
    for (int idx = t; idx < 4096; idx += 256) {
        const int r = idx >> 6, d = idx & 63;
        Qs[r][d] = g_qkv[(size_t)(b*Nn + n0 + r)*C3 + 0*Cc + h*HDd + d];
        Ks[r][d] = g_qkv[(size_t)(b*Nn + m0 + r)*C3 + 1*Cc + h*HDd + d];
    }
    __syncthreads();
    const int warp = t >> 5;
    const int wm = (warp >> 2) * 32;
    const int wn = (warp & 3) * 16;
    wmma::fragment<wmma::accumulator, 16, 16, 8, float> acc[2];
    wmma::fill_fragment(acc[0], 0.f);
    wmma::fill_fragment(acc[1], 0.f);
#pragma unroll
    for (int k8 = 0; k8 < 64; k8 += 8) {
        wmma::fragment<wmma::matrix_a, 16, 16, 8, wmma::precision::tf32, wmma::row_major> a[2];
        wmma::fragment<wmma::matrix_b, 16, 16, 8, wmma::precision::tf32, wmma::col_major> bf;
        wmma::load_matrix_sync(a[0], &Qs[wm][k8], 68);
        wmma::load_matrix_sync(a[1], &Qs[wm + 16][k8], 68);
        wmma::load_matrix_sync(bf, &Ks[wn][k8], 68);
        wmma::mma_sync(acc[0], a[0], bf, acc[0]);
        wmma::mma_sync(acc[1], a[1], bf, acc[1]);
    }
#pragma unroll
    for (int i = 0; i < 2; i++) {
#pragma unroll
        for (int e = 0; e < acc[i].num_elements; e++) acc[i].x[e] *= 0.125f;
        wmma::store_matrix_sync(g_attn + ((size_t)bh*Nn + n0 + wm + i*16)*Nn + m0 + wn,
                                acc[i], Nn, wmma::mem_row_major);
    }
}

// ---------------- softmax: one warp per row (len 320), tf32-rounded out -----
__global__ void softmax_warp() {
    const int row  = blockIdx.x * 8 + (threadIdx.x >> 5);
    const int lane = threadIdx.x & 31;
    float* p = g_attn + (size_t)row * Nn;
    float v[10];
    float m = -1e30f;
#pragma unroll
    for (int i = 0; i < 10; i++) { v[i] = p[lane + 32*i]; m = fmaxf(m, v[i]); }
#pragma unroll
    for (int o = 16; o > 0; o >>= 1) m = fmaxf(m, __shfl_xor_sync(0xffffffffu, m, o));
    float s = 0.f;
#pragma unroll
    for (int i = 0; i < 10; i++) { v[i] = expf(v[i] - m); s += v[i]; }
#pragma unroll
    for (int o = 16; o > 0; o >>= 1) s += __shfl_xor_sync(0xffffffffu, s, o);
    const float inv = 1.f / s;
#pragma unroll
    for (int i = 0; i < 10; i++) p[lane + 32*i] = to_tf32(v[i] * inv);
}

// ---------------- ctx = attn @ v (tf32 wmma, rounded output) ----------------
__global__ void __launch_bounds__(256)
ctx_wmma() {
    __shared__ float As[64][68];
    __shared__ float Vs[64][68];
    const int bh = blockIdx.y;
    const int b = bh / Hh, h = bh % Hh;
    const int n0 = blockIdx.x * 64;
    const int t = threadIdx.x;
    const int warp = t >> 5;
    const int wm = (warp >> 2) * 32;
    const int wn = (warp & 3) * 16;
    wmma::fragment<wmma::accumulator, 16, 16, 8, float> acc[2];
    wmma::fill_fragment(acc[0], 0.f);
    wmma::fill_fragment(acc[1], 0.f);
    for (int m0 = 0; m0 < Nn; m0 += 64) {
        for (int idx = t; idx < 4096; idx += 256) {
            const int r = idx >> 6, c = idx & 63;
            As[r][c] = g_attn[((size_t)bh*Nn + n0 + r)*Nn + m0 + c];
            Vs[r][c] = g_qkv[(size_t)(b*Nn + m0 + r)*C3 + 2*Cc + h*HDd + c];
        }
        __syncthreads();
#pragma unroll
        for (int k8 = 0; k8 < 64; k8 += 8) {
            wmma::fragment<wmma::matrix_a, 16, 16, 8, wmma::precision::tf32, wmma::row_major> a[2];
            wmma::fragment<wmma::matrix_b, 16, 16, 8, wmma::precision::tf32, wmma::row_major> bf;
            wmma::load_matrix_sync(a[0], &As[wm][k8], 68);
            wmma::load_matrix_sync(a[1], &As[wm + 16][k8], 68);
            wmma::load_matrix_sync(bf, &Vs[k8][wn], 68);
            wmma::mma_sync(acc[0], a[0], bf, acc[0]);
            wmma::mma_sync(acc[1], a[1], bf, acc[1]);
        }
        __syncthreads();
    }
#pragma unroll
    for (int i = 0; i < 2; i++) {
#pragma unroll
        for (int e = 0; e < acc[i].num_elements; e++)
            acc[i].x[e] = to_tf32(acc[i].x[e]);
        wmma::store_matrix_sync(g_ctx + (size_t)(b*Nn + n0 + wm + i*16)*Cc + h*HDd + wn,
                                acc[i], Cc, wmma::mem_row_major);
    }
}

// ---------------- w_ts: head-mean of attn[:, :, :LT, LT:], softmax over s ---
__global__ void wts_kernel() {
    const int b  = blockIdx.x / LT;
    const int tq = blockIdx.x % LT;
    const int s  = threadIdx.x;
    float a = 0.f;
#pragma unroll
    for (int h = 0; h < Hh; h++)
        a += g_attn[((size_t)(b*Hh + h)*Nn + tq)*Nn + LT + s];
    a *= (1.f / Hh);
    __shared__ float rbuf[8];
    __shared__ float bmax, bsum;
    float m = a;
#pragma unroll
    for (int o = 16; o > 0; o >>= 1) m = fmaxf(m, __shfl_xor_sync(0xffffffffu, m, o));
    if ((s & 31) == 0) rbuf[s >> 5] = m;
    __syncthreads();
    if (s < 32) {
        float mm = (s < 8) ? rbuf[s] : -1e30f;
#pragma unroll
        for (int o = 4; o > 0; o >>= 1) mm = fmaxf(mm, __shfl_xor_sync(0xffffffffu, mm, o));
        if (s == 0) bmax = mm;
    }
    __syncthreads();
    const float e = expf(a - bmax);
    float su = e;
#pragma unroll
    for (int o = 16; o > 0; o >>= 1) su += __shfl_xor_sync(0xffffffffu, su, o);
    __syncthreads();
    if ((s & 31) == 0) rbuf[s >> 5] = su;
    __syncthreads();
    if (s < 32) {
        float ss = (s < 8) ? rbuf[s] : 0.f;
#pragma unroll
        for (int o = 4; o > 0; o >>= 1) ss += __shfl_xor_sync(0xffffffffu, ss, o);
        if (s == 0) bsum = ss;
    }
    __syncthreads();
    g_wts[((size_t)b*LT + tq)*LS + s] = e / bsum;
}

// ---------------- graph conv (block-sparse adj) -----------------------------
__global__ void xg_top_kernel() {
    const int b  = blockIdx.x / LT;
    const int tq = blockIdx.x % LT;
    __shared__ float w[LS];
    w[threadIdx.x] = g_wts[((size_t)b*LT + tq)*LS + threadIdx.x];
    __syncthreads();
    float a0 = 0.f, a1 = 0.f, a2 = 0.f;
    const float* base = g_sup + (size_t)(b*Nn + LT)*Cc + threadIdx.x;
    for (int s = 0; s < LS; s++) {
        const float ws = w[s];
        const float* sup = base + (size_t)s*Cc;
        a0 += ws * sup[0];
        a1 += ws * sup[256];
        a2 += ws * sup[512];
    }
    float* o = g_xg + (size_t)(b*Nn + tq)*Cc + threadIdx.x;
    o[0] = a0; o[256] = a1; o[512] = a2;
}
__global__ void xg_bot_kernel() {
    const int b = blockIdx.x / LS;
    const int s = blockIdx.x % LS;
    __shared__ float w[LT];
    if (threadIdx.x < LT)
        w[threadIdx.x] = g_wts[((size_t)b*LT + threadIdx.x)*LS + s];
    __syncthreads();
    float a0 = 0.f, a1 = 0.f, a2 = 0.f;
    const float* base = g_sup + (size_t)(b*Nn)*Cc + threadIdx.x;
    for (int tq = 0; tq < LT; tq++) {
        const float wt = w[tq];
        const float* sup = base + (size_t)tq*Cc;
        a0 += wt * sup[0];
        a1 += wt * sup[256];
        a2 += wt * sup[512];
    }
    float* o = g_xg + (size_t)(b*Nn + LT + s)*Cc + threadIdx.x;
    o[0] = a0; o[256] = a1; o[512] = a2;
}

// ---------------------------------------------------------------------------
extern "C" void kernel_launch(void* const* d_in, const int* in_sizes, int n_in,
                              void* d_out, int out_size) {
    const float* x     = (const float*)d_in[0];
    const float* g1    = (const float*)d_in[3];
    const float* b1    = (const float*)d_in[4];
    const float* Wqkv  = (const float*)d_in[5];
    const float* Wproj = (const float*)d_in[6];
    const float* bproj = (const float*)d_in[7];
    const float* g2    = (const float*)d_in[8];
    const float* b2    = (const float*)d_in[9];
    const float* W1    = (const float*)d_in[10];
    const float* bm1   = (const float*)d_in[11];
    const float* W2    = (const float*)d_in[12];
    const float* bm2   = (const float*)d_in[13];
    const float* Wg    = (const float*)d_in[14];
    const float* bg    = (const float*)d_in[15];
    const float* g3    = (const float*)d_in[16];
    const float* b3    = (const float*)d_in[17];
    float* out = (float*)d_out;

    float *xn, *qkv, *ctx, *x1, *hbuf, *x2, *sup, *xg, *wbuf;
    cudaGetSymbolAddress((void**)&xn,   g_xn);
    cudaGetSymbolAddress((void**)&qkv,  g_qkv);
    cudaGetSymbolAddress((void**)&ctx,  g_ctx);
    cudaGetSymbolAddress((void**)&x1,   g_x1);
    cudaGetSymbolAddress((void**)&hbuf, g_h);
    cudaGetSymbolAddress((void**)&x2,   g_x2);
    cudaGetSymbolAddress((void**)&sup,  g_sup);
    cudaGetSymbolAddress((void**)&xg,   g_xg);
    cudaGetSymbolAddress((void**)&wbuf, g_wbuf);

    float* wqkv_t  = wbuf;
    float* wproj_t = wqkv_t  + WQKV_N;
    float* w1_t    = wproj_t + WPROJ_N;
    float* w2_t    = w1_t    + W1_N;
    float* wg_t    = w2_t    + W2_N;

    cudaFuncSetAttribute(gemm_tc<8>,  cudaFuncAttributeMaxDynamicSharedMemorySize, GEMM_SMEM);
    cudaFuncSetAttribute(gemm_tc<3>,  cudaFuncAttributeMaxDynamicSharedMemorySize, GEMM_SMEM);
    cudaFuncSetAttribute(gemm_tc<13>, cudaFuncAttributeMaxDynamicSharedMemorySize, GEMM_SMEM);
    cudaFuncSetAttribute(gemm_tc<11>, cudaFuncAttributeMaxDynamicSharedMemorySize, GEMM_SMEM);
    cudaFuncSetAttribute(gemm_tc<1>,  cudaFuncAttributeMaxDynamicSharedMemorySize, GEMM_SMEM);

    // 0. weight prep: transpose + tf32 round
    wprep<<<dim3(C3/32,   Cc/32),   dim3(32,8)>>>(Wqkv,  wqkv_t,  Cc,   C3);
    wprep<<<dim3(Cc/32,   Cc/32),   dim3(32,8)>>>(Wproj, wproj_t, Cc,   Cc);
    wprep<<<dim3(MLPH/32, Cc/32),   dim3(32,8)>>>(W1,    w1_t,    Cc,   MLPH);
    wprep<<<dim3(Cc/32,   MLPH/32), dim3(32,8)>>>(W2,    w2_t,    MLPH, Cc);
    wprep<<<dim3(Cc/32,   Cc/32),   dim3(32,8)>>>(Wg,    wg_t,    Cc,   Cc);

    // 1. xn = round(LN(x))
    ln_kernel<false, true><<<MROWS, 256>>>(x, g1, b1, xn);
    // 2. qkv = round(xn @ Wqkv)
    gemm_tc<8><<<dim3(C3/128, MROWS/128), 256, GEMM_SMEM>>>(
        xn, wqkv_t, nullptr, nullptr, qkv, MROWS, C3, Cc);
    // 3. logits
    logits_wmma<<<dim3(Nn/64, Nn/64, Bb*Hh), 256>>>();
    // 4. softmax (rounded probs)
    softmax_warp<<<Bb*Hh*Nn/8, 256>>>();
    // 5. ctx = round(attn @ v)
    ctx_wmma<<<dim3(Nn/64, Bb*Hh), 256>>>();
    // 6. x1 = x + ctx @ Wproj + bproj
    gemm_tc<3><<<dim3(Cc/128, MROWS/128), 256, GEMM_SMEM>>>(
        ctx, wproj_t, bproj, x, x1, MROWS, Cc, Cc);
    // 7. xn = round(LN(x1))
    ln_kernel<false, true><<<MROWS, 256>>>(x1, g2, b2, xn);
    // 8. h = round(gelu(xn @ W1 + bm1))
    gemm_tc<13><<<dim3(MLPH/128, MROWS/128), 256, GEMM_SMEM>>>(
        xn, w1_t, bm1, nullptr, hbuf, MROWS, MLPH, Cc);
    // 9. x2 = round(x1 + h @ W2 + bm2)
    gemm_tc<11><<<dim3(Cc/128, MROWS/128), 256, GEMM_SMEM>>>(
        hbuf, w2_t, bm2, x1, x2, MROWS, Cc, MLPH);
    // 10. w_ts
    wts_kernel<<<Bb*LT, 256>>>();
    // 11. support = x2 @ Wg + bg
    gemm_tc<1><<<dim3(Cc/128, MROWS/128), 256, GEMM_SMEM>>>(
        x2, wg_t, bg, nullptr, sup, MROWS, Cc, Cc);
    // 12. xg = adj @ support (block sparse)
    xg_top_kernel<<<Bb*LT, 256>>>();
    xg_bot_kernel<<<Bb*LS, 256>>>();
    // 13. out = xg + LN(xg)
    ln_kernel<true, false><<<MROWS, 256>>>(xg, g3, b3, out);
}